// round 9
// baseline (speedup 1.0000x reference)
#include <cuda_runtime.h>

// ---------------------------------------------------------------------------
// 2-layer LSTM (H=51), T=2048 + 16 autoregressive steps, B=512.
// R9 (= R7/R8 resubmit; both hit broker infra failures, never executed):
// k-THIRDS split -> 21 warps (672 thr) for issue saturation.
//   q=0: warps 0-6   (thr   0..203 work, 204..211 out/x spares), k [0,20),  5 chunks
//   q=1: warps 7-13  (thr 224..427 work), k [20,36), 4 chunks, owns c2 (update2)
//   q=2: warps 14-20 (thr 448..651 work), k [36,52), 4 chunks, owns c1 (update1)
// Partials at gate-buffer col 4r+q (col 3 = 0) -> update reads one float4/gate.
// Weights in registers (<=30 u64/thread), templated chunk counts (no dyn idx).
// 4 barriers per main step; out-dot + x-prefetch concurrent with gate1.
// ---------------------------------------------------------------------------

#define H     51
#define G4    204
#define T     2048
#define FUT   16
#define TT    (T + FUT)
#define NB    4
#define NBLK  128
#define WPAD  52          // h row pitch (float; h[51] = 0)
#define GPIT  816         // gate buffer pitch = 4 * G4
#define NTH   672         // 21 warps

typedef unsigned long long u64;

__device__ __forceinline__ u64 pack2(float lo, float hi) {
    u64 r; asm("mov.b64 %0, {%1,%2};" : "=l"(r) : "f"(lo), "f"(hi)); return r;
}
__device__ __forceinline__ u64 ffma2(u64 a, u64 b, u64 c) {
    u64 d; asm("fma.rn.f32x2 %0, %1, %2, %3;" : "=l"(d) : "l"(a), "l"(b), "l"(c));
    return d;
}
__device__ __forceinline__ float hsum2(u64 a) {
    float lo, hi; asm("mov.b64 {%0,%1}, %2;" : "=f"(lo), "=f"(hi) : "l"(a));
    return lo + hi;
}
__device__ __forceinline__ float sigf(float x) {
    return __fdividef(1.f, 1.f + __expf(-x));
}
__device__ __forceinline__ float tanh_fast(float x) {
    float xc = fminf(fmaxf(x, -15.f), 15.f);
    float e  = __expf(2.f * xc);
    return __fdividef(e - 1.f, e + 1.f);
}
__device__ __forceinline__ float lstm_act(float gi, float gf, float gg, float go, float& c) {
    c = sigf(gf) * c + sigf(gi) * tanh_fast(gg);
    return sigf(go) * tanh_fast(c);
}

struct __align__(16) Smem {
    float h1[NB][WPAD];
    float h2[NB][WPAD];
    float G1[NB][GPIT];     // partials at col 4r+q; col 4r+3 stays 0
    float G2[NB][GPIT];
    float WL[WPAD];         // W_lin (WL[51]=0)
    float X[NB];
    float OUTB[NB];
    float blin;
};

// load up to 5 float4 chunks (nc valid) starting at float offset ko, as f32x2 pairs
__device__ __forceinline__ void load_third(const float* row, int ko, int nc, u64* w) {
    #pragma unroll
    for (int c = 0; c < 5; c++) {
        #pragma unroll
        for (int qq = 0; qq < 2; qq++) {
            int k0 = ko + 4 * c + 2 * qq, k1 = k0 + 1;
            bool v = (c < nc);
            float a = (v && k0 < H) ? row[k0] : 0.f;
            float b = (v && k1 < H) ? row[k1] : 0.f;
            w[2 * c + qq] = pack2(a, b);
        }
    }
}

template<int NC>
__device__ __forceinline__ void dot1(const float (*h)[WPAD], int ko,
                                     const u64* w, u64* acc) {
    #pragma unroll
    for (int c = 0; c < NC; c++) {
        #pragma unroll
        for (int b = 0; b < NB; b++) {
            ulonglong2 hv = *(const ulonglong2*)&h[b][ko + 4 * c];
            acc[b] = ffma2(w[2 * c],     hv.x, acc[b]);
            acc[b] = ffma2(w[2 * c + 1], hv.y, acc[b]);
        }
    }
}

template<int NC>
__device__ __forceinline__ void dot2(const float (*ha)[WPAD], const float (*hb)[WPAD],
                                     int ko, const u64* wa, const u64* wb, u64* acc) {
    #pragma unroll
    for (int c = 0; c < NC; c++) {
        #pragma unroll
        for (int b = 0; b < NB; b++) {
            ulonglong2 hav = *(const ulonglong2*)&ha[b][ko + 4 * c];
            ulonglong2 hbv = *(const ulonglong2*)&hb[b][ko + 4 * c];
            acc[b] = ffma2(wa[2 * c],     hav.x, acc[b]);
            acc[b] = ffma2(wa[2 * c + 1], hav.y, acc[b]);
            acc[b] = ffma2(wb[2 * c],     hbv.x, acc[b]);
            acc[b] = ffma2(wb[2 * c + 1], hbv.y, acc[b]);
        }
    }
}

// sum the 3 partials of one gate (col 4*row .. 4*row+2; col 3 is zero)
__device__ __forceinline__ float gsum(const float* grow, int row) {
    float4 v = *(const float4*)&grow[4 * row];
    return (v.x + v.y) + (v.z + v.w);
}

__global__ __launch_bounds__(NTH, 1)
void lstm_k3_kernel(const float* __restrict__ input,
                    const float* __restrict__ Wih1,
                    const float* __restrict__ Whh1,
                    const float* __restrict__ bih1,
                    const float* __restrict__ bhh1,
                    const float* __restrict__ Wih2,
                    const float* __restrict__ Whh2,
                    const float* __restrict__ bih2,
                    const float* __restrict__ bhh2,
                    const float* __restrict__ Wlin,
                    const float* __restrict__ blin,
                    float* __restrict__ out)
{
    __shared__ Smem s;
    const int j   = threadIdx.x;
    const int bb0 = blockIdx.x * NB;

    const int  q    = j / 224;              // k-third (uniform per warp)
    const int  rr   = j - q * 224;
    const bool work = (rr < G4);
    const int  r    = rr;                   // gate row
    const bool isOut = (q == 0 && rr >= 204 && rr < 208);
    const bool isX   = (q == 0 && rr >= 208 && rr < 212);
    const int  ko   = (q == 0) ? 0 : (q == 1 ? 20 : 36);
    const int  nc   = (q == 0) ? 5 : 4;

    // ---------------- prologue: third-row weights to registers ----------------
    u64 w1p[10], wap[10], wbp[10];
    float bj1 = 0.f, bj2 = 0.f, wi1 = 0.f;
    if (work) {
        load_third(Whh1 + r * H, ko, nc, w1p);
        load_third(Wih2 + r * H, ko, nc, wap);
        load_third(Whh2 + r * H, ko, nc, wbp);
        if (q == 0) {                        // bias & input terms only in third 0
            bj1 = bih1[r] + bhh1[r];
            wi1 = Wih1[r];
            bj2 = bih2[r] + bhh2[r];
        }
    }

    // update ownership: q==2 owns c1 (update1), q==1 owns c2 (update2)
    const int b1 = work ? (r / H) : 0;
    const int u1 = work ? (r % H) : 0;
    float c1 = 0.f, c2 = 0.f;

    // init shared state (G buffers fully zeroed once -> col 4r+3 stays 0)
    for (int idx = j; idx < NB * GPIT; idx += NTH) {
        (&s.G1[0][0])[idx] = 0.f;
        (&s.G2[0][0])[idx] = 0.f;
    }
    for (int idx = j; idx < NB * WPAD; idx += NTH) {
        (&s.h1[0][0])[idx] = 0.f;
        (&s.h2[0][0])[idx] = 0.f;
    }
    if (j < WPAD) s.WL[j] = (j < H) ? Wlin[j] : 0.f;
    if (j < NB) {
        s.X[j]    = input[(size_t)(bb0 + j) * T];
        s.OUTB[j] = 0.f;
    }
    if (j == 0) s.blin = blin[0];

    // ------------------------------ main loop (t = 0..T-1) ------------------------------
    for (int t = 0; t < T; t++) {
        __syncthreads();                                        // S1
        float xr = 0.f;

        // phase A: gate1 partials + out-dot(t-1) + x prefetch
        if (work) {
            u64 acc[NB];
            #pragma unroll
            for (int b = 0; b < NB; b++)
                acc[b] = (q == 0) ? pack2(fmaf(wi1, s.X[b], bj1), 0.f)
                                  : pack2(0.f, 0.f);
            if (q == 0) dot1<5>(s.h1, ko, w1p, acc);
            else        dot1<4>(s.h1, ko, w1p, acc);
            #pragma unroll
            for (int b = 0; b < NB; b++) s.G1[b][4 * r + q] = hsum2(acc[b]);
        }
        if (isOut && t >= 1) {                     // output for step t-1
            const int b = rr - 204;
            float a0 = 0.f, a1 = 0.f, a2 = 0.f, a3 = 0.f;
            #pragma unroll
            for (int p = 0; p < 13; p++) {
                float4 w = *(const float4*)&s.WL[4 * p];
                float4 h = *(const float4*)&s.h2[b][4 * p];
                a0 = fmaf(w.x, h.x, a0);  a1 = fmaf(w.y, h.y, a1);
                a2 = fmaf(w.z, h.z, a2);  a3 = fmaf(w.w, h.w, a3);
            }
            out[(size_t)(bb0 + b) * TT + (t - 1)] = (a0 + a1) + (a2 + a3) + s.blin;
        }
        if (isX) {
            int b = rr - 208;
            xr = (t + 1 < T) ? input[(size_t)(bb0 + b) * T + (t + 1)] : 0.f;
        }
        __syncthreads();                                        // S2: G1 visible

        // phase B: update1 (q==2 workers own c1)
        if (work && q == 2) {
            const float* grow = s.G1[b1];
            s.h1[b1][u1] = lstm_act(gsum(grow, u1),         gsum(grow, H + u1),
                                    gsum(grow, 2 * H + u1), gsum(grow, 3 * H + u1), c1);
        }
        __syncthreads();                                        // S3: h1 visible

        // phase C: gate2 partials
        if (work) {
            u64 acc[NB];
            #pragma unroll
            for (int b = 0; b < NB; b++)
                acc[b] = (q == 0) ? pack2(bj2, 0.f) : pack2(0.f, 0.f);
            if (q == 0) dot2<5>(s.h1, s.h2, ko, wap, wbp, acc);
            else        dot2<4>(s.h1, s.h2, ko, wap, wbp, acc);
            #pragma unroll
            for (int b = 0; b < NB; b++) s.G2[b][4 * r + q] = hsum2(acc[b]);
        }
        __syncthreads();                                        // S4: G2 visible

        // phase D: update2 (q==1 workers own c2) + publish x
        if (work && q == 1) {
            const float* grow = s.G2[b1];
            s.h2[b1][u1] = lstm_act(gsum(grow, u1),         gsum(grow, H + u1),
                                    gsum(grow, 2 * H + u1), gsum(grow, 3 * H + u1), c2);
        }
        if (isX) s.X[rr - 208] = xr;
    }

    // ---------------------- autoregressive tail (t = T..TT-1) ----------------------
    for (int t = T; t < TT; t++) {
        __syncthreads();
        // output for step t-1 -> OUTB (feeds gate1 below)
        if (isOut) {
            const int b = rr - 204;
            float a0 = 0.f, a1 = 0.f, a2 = 0.f, a3 = 0.f;
            #pragma unroll
            for (int p = 0; p < 13; p++) {
                float4 w = *(const float4*)&s.WL[4 * p];
                float4 h = *(const float4*)&s.h2[b][4 * p];
                a0 = fmaf(w.x, h.x, a0);  a1 = fmaf(w.y, h.y, a1);
                a2 = fmaf(w.z, h.z, a2);  a3 = fmaf(w.w, h.w, a3);
            }
            float val = (a0 + a1) + (a2 + a3) + s.blin;
            out[(size_t)(bb0 + b) * TT + (t - 1)] = val;
            s.OUTB[b] = val;
        }
        __syncthreads();
        if (work) {                              // gate1 with x = OUTB
            u64 acc[NB];
            #pragma unroll
            for (int b = 0; b < NB; b++)
                acc[b] = (q == 0) ? pack2(fmaf(wi1, s.OUTB[b], bj1), 0.f)
                                  : pack2(0.f, 0.f);
            if (q == 0) dot1<5>(s.h1, ko, w1p, acc);
            else        dot1<4>(s.h1, ko, w1p, acc);
            #pragma unroll
            for (int b = 0; b < NB; b++) s.G1[b][4 * r + q] = hsum2(acc[b]);
        }
        __syncthreads();
        if (work && q == 2) {
            const float* grow = s.G1[b1];
            s.h1[b1][u1] = lstm_act(gsum(grow, u1),         gsum(grow, H + u1),
                                    gsum(grow, 2 * H + u1), gsum(grow, 3 * H + u1), c1);
        }
        __syncthreads();
        if (work) {
            u64 acc[NB];
            #pragma unroll
            for (int b = 0; b < NB; b++)
                acc[b] = (q == 0) ? pack2(bj2, 0.f) : pack2(0.f, 0.f);
            if (q == 0) dot2<5>(s.h1, s.h2, ko, wap, wbp, acc);
            else        dot2<4>(s.h1, s.h2, ko, wap, wbp, acc);
            #pragma unroll
            for (int b = 0; b < NB; b++) s.G2[b][4 * r + q] = hsum2(acc[b]);
        }
        __syncthreads();
        if (work && q == 1) {
            const float* grow = s.G2[b1];
            s.h2[b1][u1] = lstm_act(gsum(grow, u1),         gsum(grow, H + u1),
                                    gsum(grow, 2 * H + u1), gsum(grow, 3 * H + u1), c2);
        }
    }

    // final output (step TT-1)
    __syncthreads();
    if (isOut) {
        const int b = rr - 204;
        float a0 = 0.f, a1 = 0.f, a2 = 0.f, a3 = 0.f;
        #pragma unroll
        for (int p = 0; p < 13; p++) {
            float4 w = *(const float4*)&s.WL[4 * p];
            float4 h = *(const float4*)&s.h2[b][4 * p];
            a0 = fmaf(w.x, h.x, a0);  a1 = fmaf(w.y, h.y, a1);
            a2 = fmaf(w.z, h.z, a2);  a3 = fmaf(w.w, h.w, a3);
        }
        out[(size_t)(bb0 + b) * TT + (TT - 1)] = (a0 + a1) + (a2 + a3) + s.blin;
    }
}

extern "C" void kernel_launch(void* const* d_in, const int* in_sizes, int n_in,
                              void* d_out, int out_size)
{
    const float* input = (const float*)d_in[0];
    const float* Wih1  = (const float*)d_in[1];
    const float* Whh1  = (const float*)d_in[2];
    const float* bih1  = (const float*)d_in[3];
    const float* bhh1  = (const float*)d_in[4];
    const float* Wih2  = (const float*)d_in[5];
    const float* Whh2  = (const float*)d_in[6];
    const float* bih2  = (const float*)d_in[7];
    const float* bhh2  = (const float*)d_in[8];
    const float* Wlin  = (const float*)d_in[9];
    const float* blin  = (const float*)d_in[10];
    float* out = (float*)d_out;

    lstm_k3_kernel<<<NBLK, NTH>>>(
        input, Wih1, Whh1, bih1, bhh1, Wih2, Whh2, bih2, bhh2, Wlin, blin, out);
}

// round 10
// speedup vs baseline: 1.8227x; 1.8227x over previous
#include <cuda_runtime.h>

// ---------------------------------------------------------------------------
// 2-layer LSTM (H=51), T=2048 + 16 autoregressive steps, B=512.
// R10: cross-layer pipeline with UNIFORM roles (spill-proof, divergence-free).
//   L1  (thr   0..203): gate1(tau)    = b1 + Wih1*x + Whh1 . h1(tau-1)
//   L2A (thr 204..407): gate2a(tau-1) = b2 + Wih2 . h1(tau-1)
//   L2B (thr 408..611): gate2b(tau-1) =      Whh2 . h2(tau-2)
//   spares (612..619) : out-dot(tau-2), x-prefetch(tau+1)
// Every worker: 26 f32x2 weight regs, identical 13-chunk x 4-batch dot.
// update1 (L1 threads, c1) + update2 (L2A threads, c2) run concurrently.
// 2 barriers per tick. Serial 5-phase epilogue for the 16 future steps.
// ---------------------------------------------------------------------------

#define H     51
#define G4    204
#define T     2048
#define FUT   16
#define TT    (T + FUT)
#define NB    4
#define NBLK  128
#define WPAD  52          // h row pitch (float; h[51] = 0)
#define G1P   208
#define G2P   416         // two partials per gate: col 2g / 2g+1
#define NTH   640         // 20 warps

typedef unsigned long long u64;

__device__ __forceinline__ u64 pack2(float lo, float hi) {
    u64 r; asm("mov.b64 %0, {%1,%2};" : "=l"(r) : "f"(lo), "f"(hi)); return r;
}
__device__ __forceinline__ u64 ffma2(u64 a, u64 b, u64 c) {
    u64 d; asm("fma.rn.f32x2 %0, %1, %2, %3;" : "=l"(d) : "l"(a), "l"(b), "l"(c));
    return d;
}
__device__ __forceinline__ float hsum2(u64 a) {
    float lo, hi; asm("mov.b64 {%0,%1}, %2;" : "=f"(lo), "=f"(hi) : "l"(a));
    return lo + hi;
}
__device__ __forceinline__ float sigf(float x) {
    return __fdividef(1.f, 1.f + __expf(-x));
}
__device__ __forceinline__ float tanh_fast(float x) {
    float xc = fminf(fmaxf(x, -15.f), 15.f);
    float e  = __expf(2.f * xc);
    return __fdividef(e - 1.f, e + 1.f);
}
__device__ __forceinline__ float lstm_act(float gi, float gf, float gg, float go, float& c) {
    c = sigf(gf) * c + sigf(gi) * tanh_fast(gg);
    return sigf(go) * tanh_fast(c);
}

struct __align__(16) Smem {
    float h1[2][NB][WPAD];   // double-buffered hidden states (pad col 51 = 0)
    float h2[2][NB][WPAD];
    float G1[NB][G1P];       // layer-1 gates (single producer per column)
    float G2[NB][G2P];       // layer-2 gate partials at cols 2g / 2g+1
    float WL[WPAD];          // W_lin padded
    float X[2][NB];          // double-buffered input scalar
    float OUTB[NB];          // latest output (autoregressive feed)
    float blin;
};

// the one dot shape every worker runs: 13 float4 chunks x 4 batches
__device__ __forceinline__ void dot13(const float* __restrict__ hb,
                                      const u64* __restrict__ w, u64* acc) {
    #pragma unroll
    for (int c = 0; c < 13; c++) {
        #pragma unroll
        for (int b = 0; b < NB; b++) {
            ulonglong2 hv = *(const ulonglong2*)(hb + b * WPAD + 4 * c);
            acc[b] = ffma2(w[2 * c],     hv.x, acc[b]);
            acc[b] = ffma2(w[2 * c + 1], hv.y, acc[b]);
        }
    }
}

__global__ __launch_bounds__(NTH, 1)
void lstm_pipe2_kernel(const float* __restrict__ input,
                       const float* __restrict__ Wih1,
                       const float* __restrict__ Whh1,
                       const float* __restrict__ bih1,
                       const float* __restrict__ bhh1,
                       const float* __restrict__ Wih2,
                       const float* __restrict__ Whh2,
                       const float* __restrict__ bih2,
                       const float* __restrict__ bhh2,
                       const float* __restrict__ Wlin,
                       const float* __restrict__ blin,
                       float* __restrict__ out)
{
    __shared__ Smem s;
    const int j   = threadIdx.x;
    const int bb0 = blockIdx.x * NB;

    const int  ro   = (j < 204) ? 0 : (j < 408 ? 1 : (j < 612 ? 2 : 3));
    const bool isW  = (ro < 3);
    const int  row  = (ro == 0) ? j : (ro == 1 ? j - 204 : (ro == 2 ? j - 408 : 0));
    const bool isOut = (j >= 612 && j < 616);
    const bool isX   = (j >= 616 && j < 620);

    // ---------------- prologue: one weight row per worker ----------------
    u64 wreg[26];
    float bj = 0.f, wi1 = 0.f;
    if (isW) {
        const float* wsrc = (ro == 0) ? (Whh1 + row * H)
                          : (ro == 1) ? (Wih2 + row * H)
                                      : (Whh2 + row * H);
        #pragma unroll
        for (int p = 0; p < 26; p++) {
            int k1 = 2 * p + 1;
            wreg[p] = pack2(wsrc[2 * p], (k1 < H) ? wsrc[k1] : 0.f);
        }
        if (ro == 0) { bj = bih1[row] + bhh1[row]; wi1 = Wih1[row]; }
        if (ro == 1) { bj = bih2[row] + bhh2[row]; }
    }

    // update ownership: ro0 thread owns c1(b1,u1); ro1 thread owns c2(b1,u1)
    const int b1 = isW ? (row / H) : 0;
    const int u1 = isW ? (row % H) : 0;
    float cc = 0.f;                       // c1 for ro0, c2 for ro1

    // init shared state
    for (int idx = j; idx < 2 * NB * WPAD; idx += NTH) {
        (&s.h1[0][0][0])[idx] = 0.f;
        (&s.h2[0][0][0])[idx] = 0.f;
    }
    if (j < WPAD) s.WL[j] = (j < H) ? Wlin[j] : 0.f;
    if (j < NB) {
        s.X[0][j]  = input[(size_t)(bb0 + j) * T];
        s.X[1][j]  = 0.f;
        s.OUTB[j]  = 0.f;
    }
    if (j == 0) s.blin = blin[0];
    __syncthreads();

    // --------------------------- pipelined main loop ---------------------------
    for (int tau = 0; tau <= T + 1; tau++) {
        const int pA = tau & 1, pB = pA ^ 1;
        const bool l1act = (tau < T);
        const bool l2act = (tau >= 1 && tau <= T);
        float xr = 0.f;

        // ================= dot phase =================
        if (isW && ((ro == 0) ? l1act : l2act)) {
            u64 acc[NB];
            if (ro == 0) {
                #pragma unroll
                for (int b = 0; b < NB; b++)
                    acc[b] = pack2(fmaf(wi1, s.X[pA][b], bj), 0.f);
            } else {
                #pragma unroll
                for (int b = 0; b < NB; b++) acc[b] = pack2(bj, 0.f);  // bj=0 for ro2
            }
            const float* hb = (ro == 2) ? &s.h2[pA][0][0] : &s.h1[pB][0][0];
            dot13(hb, wreg, acc);
            if (ro == 0) {
                #pragma unroll
                for (int b = 0; b < NB; b++) s.G1[b][row] = hsum2(acc[b]);
            } else {
                #pragma unroll
                for (int b = 0; b < NB; b++) s.G2[b][2 * row + (ro - 1)] = hsum2(acc[b]);
            }
        }
        if (isOut && tau >= 2) {                   // output for step tau-2
            const int b = j - 612;
            float a0 = 0.f, a1 = 0.f, a2 = 0.f, a3 = 0.f;
            const float* h2p = &s.h2[pA][b][0];
            #pragma unroll
            for (int p = 0; p < 13; p++) {
                float4 w = *(const float4*)&s.WL[4 * p];
                float4 h = *(const float4*)&h2p[4 * p];
                a0 = fmaf(w.x, h.x, a0);  a1 = fmaf(w.y, h.y, a1);
                a2 = fmaf(w.z, h.z, a2);  a3 = fmaf(w.w, h.w, a3);
            }
            float val = (a0 + a1) + (a2 + a3) + s.blin;
            out[(size_t)(bb0 + b) * TT + (tau - 2)] = val;
            s.OUTB[b] = val;
        }
        if (isX && tau <= T - 2)
            xr = input[(size_t)(bb0 + (j - 616)) * T + (tau + 1)];
        __syncthreads();                           // S_mid: G1/G2 visible

        // ================= update phase =================
        if (ro == 0 && l1act) {
            float gi = s.G1[b1][u1],         gf = s.G1[b1][H + u1];
            float gg = s.G1[b1][2 * H + u1], go = s.G1[b1][3 * H + u1];
            s.h1[pA][b1][u1] = lstm_act(gi, gf, gg, go, cc);
        }
        if (ro == 1 && l2act) {
            float2 vi = *(const float2*)&s.G2[b1][2 * u1];
            float2 vf = *(const float2*)&s.G2[b1][2 * (H + u1)];
            float2 vg = *(const float2*)&s.G2[b1][2 * (2 * H + u1)];
            float2 vo = *(const float2*)&s.G2[b1][2 * (3 * H + u1)];
            s.h2[pB][b1][u1] = lstm_act(vi.x + vi.y, vf.x + vf.y,
                                        vg.x + vg.y, vo.x + vo.y, cc);
        }
        if (isX && tau <= T - 2) s.X[pB][j - 616] = xr;
        __syncthreads();                           // S_end: h1[pA], h2[pB], X[pB]
    }

    // --------------------- serial autoregressive epilogue ---------------------
    for (int t = T; t < TT; t++) {
        const int pA = t & 1, pB = pA ^ 1;

        if (ro == 0) {                             // gate1, x = previous output
            u64 acc[NB];
            #pragma unroll
            for (int b = 0; b < NB; b++)
                acc[b] = pack2(fmaf(wi1, s.OUTB[b], bj), 0.f);
            dot13(&s.h1[pB][0][0], wreg, acc);
            #pragma unroll
            for (int b = 0; b < NB; b++) s.G1[b][row] = hsum2(acc[b]);
        }
        __syncthreads();
        if (ro == 0) {
            float gi = s.G1[b1][u1],         gf = s.G1[b1][H + u1];
            float gg = s.G1[b1][2 * H + u1], go = s.G1[b1][3 * H + u1];
            s.h1[pA][b1][u1] = lstm_act(gi, gf, gg, go, cc);
        }
        __syncthreads();
        if (isW && ro != 0) {                      // gate2 of step t
            u64 acc[NB];
            #pragma unroll
            for (int b = 0; b < NB; b++) acc[b] = pack2(bj, 0.f);
            const float* hb = (ro == 1) ? &s.h1[pA][0][0] : &s.h2[pB][0][0];
            dot13(hb, wreg, acc);
            #pragma unroll
            for (int b = 0; b < NB; b++) s.G2[b][2 * row + (ro - 1)] = hsum2(acc[b]);
        }
        __syncthreads();
        if (ro == 1) {
            float2 vi = *(const float2*)&s.G2[b1][2 * u1];
            float2 vf = *(const float2*)&s.G2[b1][2 * (H + u1)];
            float2 vg = *(const float2*)&s.G2[b1][2 * (2 * H + u1)];
            float2 vo = *(const float2*)&s.G2[b1][2 * (3 * H + u1)];
            s.h2[pA][b1][u1] = lstm_act(vi.x + vi.y, vf.x + vf.y,
                                        vg.x + vg.y, vo.x + vo.y, cc);
        }
        __syncthreads();
        if (isOut) {                               // out(t) -> gmem + OUTB
            const int b = j - 612;
            float a0 = 0.f, a1 = 0.f, a2 = 0.f, a3 = 0.f;
            const float* h2p = &s.h2[pA][b][0];
            #pragma unroll
            for (int p = 0; p < 13; p++) {
                float4 w = *(const float4*)&s.WL[4 * p];
                float4 h = *(const float4*)&h2p[4 * p];
                a0 = fmaf(w.x, h.x, a0);  a1 = fmaf(w.y, h.y, a1);
                a2 = fmaf(w.z, h.z, a2);  a3 = fmaf(w.w, h.w, a3);
            }
            float val = (a0 + a1) + (a2 + a3) + s.blin;
            out[(size_t)(bb0 + b) * TT + t] = val;
            s.OUTB[b] = val;
        }
        __syncthreads();
    }
}

extern "C" void kernel_launch(void* const* d_in, const int* in_sizes, int n_in,
                              void* d_out, int out_size)
{
    const float* input = (const float*)d_in[0];
    const float* Wih1  = (const float*)d_in[1];
    const float* Whh1  = (const float*)d_in[2];
    const float* bih1  = (const float*)d_in[3];
    const float* bhh1  = (const float*)d_in[4];
    const float* Wih2  = (const float*)d_in[5];
    const float* Whh2  = (const float*)d_in[6];
    const float* bih2  = (const float*)d_in[7];
    const float* bhh2  = (const float*)d_in[8];
    const float* Wlin  = (const float*)d_in[9];
    const float* blin  = (const float*)d_in[10];
    float* out = (float*)d_out;

    lstm_pipe2_kernel<<<NBLK, NTH>>>(
        input, Wih1, Whh1, bih1, bhh1, Wih2, Whh2, bih2, bhh2, Wlin, blin, out);
}